// round 14
// baseline (speedup 1.0000x reference)
#include <cuda_runtime.h>
#include <cstdint>

#define T_LEN   32768
#define NROWS   1024
#define CELEMS  512                     // elements per chunk
#define NCHUNK  (T_LEN / CELEMS)        // 64 chunks per row
#define STAGES  6
#define STAGE_BYTES 4096                // 2 KB P + 2 KB Q

__device__ double g_partial[NROWS];
__device__ unsigned int g_count;

__device__ __forceinline__ void mbar_init(uint32_t m, uint32_t cnt) {
    asm volatile("mbarrier.init.shared::cta.b64 [%0], %1;" :: "r"(m), "r"(cnt) : "memory");
}
__device__ __forceinline__ void mbar_expect_tx(uint32_t m, uint32_t bytes) {
    asm volatile("mbarrier.arrive.expect_tx.shared::cta.b64 _, [%0], %1;"
                 :: "r"(m), "r"(bytes) : "memory");
}
__device__ __forceinline__ void bulk_g2s(uint32_t dst, const void* src, uint32_t bytes, uint32_t m) {
    asm volatile("cp.async.bulk.shared::cta.global.mbarrier::complete_tx::bytes "
                 "[%0], [%1], %2, [%3];"
                 :: "r"(dst), "l"(src), "r"(bytes), "r"(m) : "memory");
}
__device__ __forceinline__ void mbar_wait(uint32_t m, uint32_t phase) {
    uint32_t done;
    asm volatile(
        "{\n\t.reg .pred p;\n\t"
        "mbarrier.try_wait.parity.acquire.cta.shared::cta.b64 p, [%1], %2;\n\t"
        "selp.b32 %0, 1, 0, p;\n\t}"
        : "=r"(done) : "r"(m), "r"(phase) : "memory");
    if (!done) {
        asm volatile(
            "{\n\t.reg .pred P1;\n\t"
            "WL_%=:\n\t"
            "mbarrier.try_wait.parity.acquire.cta.shared::cta.b64 P1, [%0], %1, 0x989680;\n\t"
            "@P1 bra.uni WD_%=;\n\t"
            "bra.uni WL_%=;\n\t"
            "WD_%=:\n\t}"
            :: "r"(m), "r"(phase) : "memory");
    }
}

__global__ void __launch_bounds__(32, 7)
wass_kernel(const float* __restrict__ yp, const float* __restrict__ yt,
            float* __restrict__ out) {
    __shared__ alignas(1024) float4 smem[STAGES * 256];   // 24 KB (256 f4/stage)
    __shared__ alignas(8) unsigned long long mbar[STAGES];
    __shared__ bool is_last;

    const int lane = threadIdx.x;
    const int row  = blockIdx.x;

    const float* __restrict__ prow = yp + (long)row * T_LEN;
    const float* __restrict__ trow = yt + (long)row * T_LEN;
    const uint32_t sbase = (uint32_t)__cvta_generic_to_shared(smem);
    const uint32_t mbase = (uint32_t)__cvta_generic_to_shared(mbar);

    if (lane == 0) {
        #pragma unroll
        for (int s = 0; s < STAGES; s++) mbar_init(mbase + s * 8u, 1u);
    }
    __syncwarp();

    // Issue one stage: expect 4KB, two 2KB bulk copies. Lane 0 only.
    auto issue = [&](int stage, int chunk) {
        uint32_t m  = mbase + (uint32_t)stage * 8u;
        uint32_t dP = sbase + (uint32_t)stage * (uint32_t)STAGE_BYTES;
        mbar_expect_tx(m, (uint32_t)STAGE_BYTES);
        bulk_g2s(dP,          prow + chunk * CELEMS, 2048u, m);
        bulk_g2s(dP + 2048u,  trow + chunk * CELEMS, 2048u, m);
    };

    // Prologue: fill ALL 6 stages (chunks 0..5) -> 24 KB committed per warp.
    if (lane == 0) {
        #pragma unroll
        for (int s = 0; s < STAGES; s++) issue(s, s);
    }

    double dacc = 0.0;
    float  carry = 0.0f;

    int s = 0, par = 0;                  // stage index and phase parity
    for (int f = 0; f < NCHUNK; f++) {
        // Lane-0-only wait, broadcast via syncwarp.
        if (lane == 0) mbar_wait(mbase + (uint32_t)s * 8u, (uint32_t)par);
        __syncwarp();

        // Consume stage s: lane owns 4-element runs at stride 128 (conflict-free).
        const float4* sp = smem + s * 256;        // [0,128): P, [128,256): Q
        float lp[4][4];
        float r0, r1, r2, r3;
        #pragma unroll
        for (int j = 0; j < 4; j++) {
            float4 Pj = sp[lane + 32 * j];
            float4 Qj = sp[128 + lane + 32 * j];
            float d0 = Pj.x - Qj.x, d1 = Pj.y - Qj.y;
            float d2 = Pj.z - Qj.z, d3 = Pj.w - Qj.w;
            lp[j][0] = d0;
            lp[j][1] = d0 + d1;
            lp[j][2] = lp[j][1] + d2;
            lp[j][3] = lp[j][2] + d3;
        }
        r0 = lp[0][3]; r1 = lp[1][3]; r2 = lp[2][3]; r3 = lp[3][3];

        // All lanes done reading stage s -> refill it IMMEDIATELY (before compute).
        __syncwarp();
        if (lane == 0 && f + STAGES < NCHUNK) issue(s, f + STAGES);

        // 4 independent warp scans (overlapping shfl chains).
        float i0 = r0, i1 = r1, i2 = r2, i3 = r3;
        #pragma unroll
        for (int o = 1; o < 32; o <<= 1) {
            float y0 = __shfl_up_sync(0xffffffffu, i0, o);
            float y1 = __shfl_up_sync(0xffffffffu, i1, o);
            float y2 = __shfl_up_sync(0xffffffffu, i2, o);
            float y3 = __shfl_up_sync(0xffffffffu, i3, o);
            if (lane >= o) { i0 += y0; i1 += y1; i2 += y2; i3 += y3; }
        }
        float S0 = __shfl_sync(0xffffffffu, i0, 31);
        float S1 = __shfl_sync(0xffffffffu, i1, 31);
        float S2 = __shfl_sync(0xffffffffu, i2, 31);
        float S3 = __shfl_sync(0xffffffffu, i3, 31);

        float G0 = carry;
        float G1 = G0 + S0;
        float G2 = G1 + S1;
        float G3 = G2 + S2;
        carry = G3 + S3;

        float b0 = G0 + (i0 - r0);
        float b1 = G1 + (i1 - r1);
        float b2 = G2 + (i2 - r2);
        float b3 = G3 + (i3 - r3);

        // Weighted |cumsum| accumulation: idx = f*512 + 128j + 4*lane + i.
        const float wbase = (float)(T_LEN - (f * CELEMS + 4 * lane));
        float a0 = 0.0f, a1 = 0.0f, a2 = 0.0f, a3 = 0.0f;
        #pragma unroll
        for (int j = 0; j < 4; j++) {
            float bj = (j == 0) ? b0 : (j == 1) ? b1 : (j == 2) ? b2 : b3;
            float wj = wbase - (float)(128 * j);
            a0 = fmaf(fabsf(bj + lp[j][0]), wj,        a0);
            a1 = fmaf(fabsf(bj + lp[j][1]), wj - 1.0f, a1);
            a2 = fmaf(fabsf(bj + lp[j][2]), wj - 2.0f, a2);
            a3 = fmaf(fabsf(bj + lp[j][3]), wj - 3.0f, a3);
        }
        dacc += (double)((a0 + a1) + (a2 + a3));

        // Advance ring.
        if (++s == STAGES) { s = 0; par ^= 1; }
    }

    // Warp reduction of dacc (deterministic).
    #pragma unroll
    for (int o = 16; o > 0; o >>= 1)
        dacc += __shfl_down_sync(0xffffffffu, dacc, o);
    if (lane == 0) {
        g_partial[row] = dacc;
        __threadfence();
        unsigned int prev = atomicAdd(&g_count, 1u);
        is_last = (prev == (unsigned int)(gridDim.x - 1));
    }
    __syncwarp();
    int last = __shfl_sync(0xffffffffu, (int)is_last, 0);

    // Last block: final deterministic reduce of 1024 partials with one warp.
    if (last) {
        if (lane == 0) g_count = 0;   // reset for graph replay
        double v = 0.0;
        #pragma unroll
        for (int j = 0; j < NROWS / 32; j++)
            v += g_partial[lane * (NROWS / 32) + j];
        #pragma unroll
        for (int o = 16; o > 0; o >>= 1)
            v += __shfl_down_sync(0xffffffffu, v, o);
        if (lane == 0) {
            double tc = (double)T_LEN * 16.0;            // T*C
            double scale = 2.0 / (tc * (tc + 1.0));
            out[0] = (float)((v / 64.0) * scale);        // mean over B=64
        }
    }
}

extern "C" void kernel_launch(void* const* d_in, const int* in_sizes, int n_in,
                              void* d_out, int out_size) {
    (void)in_sizes; (void)n_in; (void)out_size;
    const float* y_pred = (const float*)d_in[0];
    const float* y_true = (const float*)d_in[1];
    float* out = (float*)d_out;
    wass_kernel<<<NROWS, 32>>>(y_pred, y_true, out);
}

// round 15
// speedup vs baseline: 4.7537x; 4.7537x over previous
#include <cuda_runtime.h>
#include <cstdint>

#define T_LEN   32768
#define NROWS   1024
#define CELEMS  512                     // elements per chunk
#define NCHUNK  (T_LEN / CELEMS)        // 64 chunks per row
#define STAGES  6
#define STAGE_F4 256                    // 128 f4 P + 128 f4 Q = 4 KB per stage

__device__ double g_partial[NROWS];
__device__ unsigned int g_count;

__device__ __forceinline__ void mbar_init(uint32_t m, uint32_t cnt) {
    asm volatile("mbarrier.init.shared::cta.b64 [%0], %1;" :: "r"(m), "r"(cnt) : "memory");
}
__device__ __forceinline__ void mbar_expect_tx(uint32_t m, uint32_t bytes) {
    asm volatile("mbarrier.arrive.expect_tx.shared::cta.b64 _, [%0], %1;"
                 :: "r"(m), "r"(bytes) : "memory");
}
__device__ __forceinline__ void bulk_g2s(uint32_t dst, const void* src, uint32_t bytes, uint32_t m) {
    asm volatile("cp.async.bulk.shared::cta.global.mbarrier::complete_tx::bytes "
                 "[%0], [%1], %2, [%3];"
                 :: "r"(dst), "l"(src), "r"(bytes), "r"(m) : "memory");
}
// ALL-LANE wait (R12-proven): fast-path try_wait, then poll loop. Never 1-lane.
__device__ __forceinline__ void mbar_wait(uint32_t m, uint32_t phase) {
    uint32_t done;
    asm volatile(
        "{\n\t.reg .pred p;\n\t"
        "mbarrier.try_wait.parity.acquire.cta.shared::cta.b64 p, [%1], %2;\n\t"
        "selp.b32 %0, 1, 0, p;\n\t}"
        : "=r"(done) : "r"(m), "r"(phase) : "memory");
    if (!done) {
        asm volatile(
            "{\n\t.reg .pred P1;\n\t"
            "WL_%=:\n\t"
            "mbarrier.try_wait.parity.acquire.cta.shared::cta.b64 P1, [%0], %1, 0x989680;\n\t"
            "@P1 bra.uni WD_%=;\n\t"
            "bra.uni WL_%=;\n\t"
            "WD_%=:\n\t}"
            :: "r"(m), "r"(phase) : "memory");
    }
}

__global__ void __launch_bounds__(32, 7)
wass_kernel(const float* __restrict__ yp, const float* __restrict__ yt,
            float* __restrict__ out) {
    __shared__ alignas(1024) float4 smem[STAGES * STAGE_F4];   // 24 KB
    __shared__ alignas(8) unsigned long long mbar[STAGES];
    __shared__ bool is_last;

    const int lane = threadIdx.x;
    const int row  = blockIdx.x;

    const float* __restrict__ prow = yp + (long)row * T_LEN;
    const float* __restrict__ trow = yt + (long)row * T_LEN;
    const uint32_t sbase = (uint32_t)__cvta_generic_to_shared(smem);
    const uint32_t mbase = (uint32_t)__cvta_generic_to_shared(mbar);

    if (lane == 0) {
        #pragma unroll
        for (int s = 0; s < STAGES; s++) mbar_init(mbase + s * 8u, 1u);
    }
    __syncwarp();

    // Issue one stage: expect 4KB, two 2KB bulk copies. Lane 0 only issues.
    auto issue = [&](int stage, int chunk) {
        uint32_t m  = mbase + (uint32_t)stage * 8u;
        uint32_t dP = sbase + (uint32_t)stage * 4096u;
        mbar_expect_tx(m, 4096u);
        bulk_g2s(dP,          prow + chunk * CELEMS, 2048u, m);
        bulk_g2s(dP + 2048u,  trow + chunk * CELEMS, 2048u, m);
    };

    // Prologue: chunks 0..4 into stages 0..4 (5 stages / 20 KB committed).
    if (lane == 0) { issue(0, 0); issue(1, 1); issue(2, 2); issue(3, 3); issue(4, 4); }

    double dacc = 0.0;
    float  carry = 0.0f;

    int s = 0, par = 0;                 // stage f%6, parity (f/6)&1
    for (int f = 0; f < NCHUNK; f++) {
        // R12-proven: ALL lanes wait (acquire + instant wake).
        mbar_wait(mbase + (uint32_t)s * 8u, (uint32_t)par);
        __syncwarp();

        // Refill the stage consumed last iteration ((s+5)%6) with chunk f+5.
        const int nc = f + STAGES - 1;
        if (nc < NCHUNK && lane == 0) {
            int rs = s - 1; if (rs < 0) rs = STAGES - 1;
            issue(rs, nc);
        }

        // Consume stage s: lane owns 4-element runs at stride 128 (conflict-free).
        const float4* sp = smem + s * STAGE_F4;    // [0,128): P, [128,256): Q
        float lp[4][4];
        float r0, r1, r2, r3;
        #pragma unroll
        for (int j = 0; j < 4; j++) {
            float4 Pj = sp[lane + 32 * j];
            float4 Qj = sp[128 + lane + 32 * j];
            float d0 = Pj.x - Qj.x, d1 = Pj.y - Qj.y;
            float d2 = Pj.z - Qj.z, d3 = Pj.w - Qj.w;
            lp[j][0] = d0;
            lp[j][1] = d0 + d1;
            lp[j][2] = lp[j][1] + d2;
            lp[j][3] = lp[j][2] + d3;
        }
        r0 = lp[0][3]; r1 = lp[1][3]; r2 = lp[2][3]; r3 = lp[3][3];

        // 4 independent warp scans (overlapping shfl chains).
        float i0 = r0, i1 = r1, i2 = r2, i3 = r3;
        #pragma unroll
        for (int o = 1; o < 32; o <<= 1) {
            float y0 = __shfl_up_sync(0xffffffffu, i0, o);
            float y1 = __shfl_up_sync(0xffffffffu, i1, o);
            float y2 = __shfl_up_sync(0xffffffffu, i2, o);
            float y3 = __shfl_up_sync(0xffffffffu, i3, o);
            if (lane >= o) { i0 += y0; i1 += y1; i2 += y2; i3 += y3; }
        }
        float S0 = __shfl_sync(0xffffffffu, i0, 31);
        float S1 = __shfl_sync(0xffffffffu, i1, 31);
        float S2 = __shfl_sync(0xffffffffu, i2, 31);
        float S3 = __shfl_sync(0xffffffffu, i3, 31);

        float G0 = carry;
        float G1 = G0 + S0;
        float G2 = G1 + S1;
        float G3 = G2 + S2;
        carry = G3 + S3;

        float b0 = G0 + (i0 - r0);
        float b1 = G1 + (i1 - r1);
        float b2 = G2 + (i2 - r2);
        float b3 = G3 + (i3 - r3);

        // Weighted |cumsum| accumulation: idx = f*512 + 128j + 4*lane + i.
        const float wbase = (float)(T_LEN - (f * CELEMS + 4 * lane));
        float a0 = 0.0f, a1 = 0.0f, a2 = 0.0f, a3 = 0.0f;
        #pragma unroll
        for (int j = 0; j < 4; j++) {
            float bj = (j == 0) ? b0 : (j == 1) ? b1 : (j == 2) ? b2 : b3;
            float wj = wbase - (float)(128 * j);
            a0 = fmaf(fabsf(bj + lp[j][0]), wj,        a0);
            a1 = fmaf(fabsf(bj + lp[j][1]), wj - 1.0f, a1);
            a2 = fmaf(fabsf(bj + lp[j][2]), wj - 2.0f, a2);
            a3 = fmaf(fabsf(bj + lp[j][3]), wj - 3.0f, a3);
        }
        dacc += (double)((a0 + a1) + (a2 + a3));

        // Advance ring: s = f%6, par flips each wrap.
        if (++s == STAGES) { s = 0; par ^= 1; }
    }

    // Warp reduction of dacc (deterministic).
    #pragma unroll
    for (int o = 16; o > 0; o >>= 1)
        dacc += __shfl_down_sync(0xffffffffu, dacc, o);
    if (lane == 0) {
        g_partial[row] = dacc;
        __threadfence();
        unsigned int prev = atomicAdd(&g_count, 1u);
        is_last = (prev == (unsigned int)(gridDim.x - 1));
    }
    __syncwarp();
    int last = __shfl_sync(0xffffffffu, (int)is_last, 0);

    // Last block: final deterministic reduce of 1024 partials with one warp.
    if (last) {
        if (lane == 0) g_count = 0;   // reset for graph replay
        double v = 0.0;
        #pragma unroll
        for (int j = 0; j < NROWS / 32; j++)
            v += g_partial[lane * (NROWS / 32) + j];
        #pragma unroll
        for (int o = 16; o > 0; o >>= 1)
            v += __shfl_down_sync(0xffffffffu, v, o);
        if (lane == 0) {
            double tc = (double)T_LEN * 16.0;            // T*C
            double scale = 2.0 / (tc * (tc + 1.0));
            out[0] = (float)((v / 64.0) * scale);        // mean over B=64
        }
    }
}

extern "C" void kernel_launch(void* const* d_in, const int* in_sizes, int n_in,
                              void* d_out, int out_size) {
    (void)in_sizes; (void)n_in; (void)out_size;
    const float* y_pred = (const float*)d_in[0];
    const float* y_true = (const float*)d_in[1];
    float* out = (float*)d_out;
    wass_kernel<<<NROWS, 32>>>(y_pred, y_true, out);
}

// round 16
// speedup vs baseline: 4.9318x; 1.0375x over previous
#include <cuda_runtime.h>
#include <cstdint>

#define T_LEN   32768
#define NROWS   1024
#define CELEMS  1024                    // elements per stage (chunk)
#define NCHUNK  (T_LEN / CELEMS)        // 32 chunks per row
#define STAGES  3
#define STAGE_F4 512                    // 256 f4 P + 256 f4 Q = 8 KB per stage

__device__ double g_partial[NROWS];
__device__ unsigned int g_count;

__device__ __forceinline__ void mbar_init(uint32_t m, uint32_t cnt) {
    asm volatile("mbarrier.init.shared::cta.b64 [%0], %1;" :: "r"(m), "r"(cnt) : "memory");
}
__device__ __forceinline__ void mbar_expect_tx(uint32_t m, uint32_t bytes) {
    asm volatile("mbarrier.arrive.expect_tx.shared::cta.b64 _, [%0], %1;"
                 :: "r"(m), "r"(bytes) : "memory");
}
__device__ __forceinline__ void bulk_g2s(uint32_t dst, const void* src, uint32_t bytes, uint32_t m) {
    asm volatile("cp.async.bulk.shared::cta.global.mbarrier::complete_tx::bytes "
                 "[%0], [%1], %2, [%3];"
                 :: "r"(dst), "l"(src), "r"(bytes), "r"(m) : "memory");
}
// ALL-LANE wait (R12-proven). Never single-lane (R14 lesson).
__device__ __forceinline__ void mbar_wait(uint32_t m, uint32_t phase) {
    uint32_t done;
    asm volatile(
        "{\n\t.reg .pred p;\n\t"
        "mbarrier.try_wait.parity.acquire.cta.shared::cta.b64 p, [%1], %2;\n\t"
        "selp.b32 %0, 1, 0, p;\n\t}"
        : "=r"(done) : "r"(m), "r"(phase) : "memory");
    if (!done) {
        asm volatile(
            "{\n\t.reg .pred P1;\n\t"
            "WL_%=:\n\t"
            "mbarrier.try_wait.parity.acquire.cta.shared::cta.b64 P1, [%0], %1, 0x989680;\n\t"
            "@P1 bra.uni WD_%=;\n\t"
            "bra.uni WL_%=;\n\t"
            "WD_%=:\n\t}"
            :: "r"(m), "r"(phase) : "memory");
    }
}

__global__ void __launch_bounds__(32, 7)
wass_kernel(const float* __restrict__ yp, const float* __restrict__ yt,
            float* __restrict__ out) {
    __shared__ alignas(1024) float4 smem[STAGES * STAGE_F4];   // 24 KB
    __shared__ alignas(8) unsigned long long mbar[STAGES];
    __shared__ bool is_last;

    const int lane = threadIdx.x;
    const int row  = blockIdx.x;

    const float* __restrict__ prow = yp + (long)row * T_LEN;
    const float* __restrict__ trow = yt + (long)row * T_LEN;
    const uint32_t sbase = (uint32_t)__cvta_generic_to_shared(smem);
    const uint32_t mbase = (uint32_t)__cvta_generic_to_shared(mbar);

    if (lane == 0) {
        #pragma unroll
        for (int s = 0; s < STAGES; s++) mbar_init(mbase + s * 8u, 1u);
    }
    __syncwarp();

    // Issue one stage: expect 8 KB, two 4 KB bulk copies. Lane 0 only.
    auto issue = [&](int stage, int chunk) {
        uint32_t m  = mbase + (uint32_t)stage * 8u;
        uint32_t dP = sbase + (uint32_t)stage * 8192u;
        mbar_expect_tx(m, 8192u);
        bulk_g2s(dP,          prow + chunk * CELEMS, 4096u, m);
        bulk_g2s(dP + 4096u,  trow + chunk * CELEMS, 4096u, m);
    };

    // Prologue: chunks 0,1 into stages 0,1 (16 KB committed).
    if (lane == 0) { issue(0, 0); issue(1, 1); }

    double dacc = 0.0;
    float  carry = 0.0f;

    int s = 0, par = 0;                 // stage f%3, parity (f/3)&1
    for (int f = 0; f < NCHUNK; f++) {
        mbar_wait(mbase + (uint32_t)s * 8u, (uint32_t)par);
        __syncwarp();   // all lanes past last iteration's reads AND this wait

        // Refill the stage consumed last iteration ((s+2)%3) with chunk f+2.
        if (lane == 0 && f + 2 < NCHUNK) {
            int rs = s - 1; if (rs < 0) rs = STAGES - 1;
            issue(rs, f + 2);
        }

        const float4* sp = smem + s * STAGE_F4;    // [0,256): P, [256,512): Q

        // Two 512-element sub-chunks (identical numerics to R12).
        #pragma unroll
        for (int h = 0; h < 2; h++) {
            const int po = h * 128;
            float lp[4][4];
            float r0, r1, r2, r3;
            #pragma unroll
            for (int j = 0; j < 4; j++) {
                float4 Pj = sp[po + lane + 32 * j];
                float4 Qj = sp[256 + po + lane + 32 * j];
                float d0 = Pj.x - Qj.x, d1 = Pj.y - Qj.y;
                float d2 = Pj.z - Qj.z, d3 = Pj.w - Qj.w;
                lp[j][0] = d0;
                lp[j][1] = d0 + d1;
                lp[j][2] = lp[j][1] + d2;
                lp[j][3] = lp[j][2] + d3;
            }
            r0 = lp[0][3]; r1 = lp[1][3]; r2 = lp[2][3]; r3 = lp[3][3];

            // 4 independent warp scans (overlapping shfl chains).
            float i0 = r0, i1 = r1, i2 = r2, i3 = r3;
            #pragma unroll
            for (int o = 1; o < 32; o <<= 1) {
                float y0 = __shfl_up_sync(0xffffffffu, i0, o);
                float y1 = __shfl_up_sync(0xffffffffu, i1, o);
                float y2 = __shfl_up_sync(0xffffffffu, i2, o);
                float y3 = __shfl_up_sync(0xffffffffu, i3, o);
                if (lane >= o) { i0 += y0; i1 += y1; i2 += y2; i3 += y3; }
            }
            float S0 = __shfl_sync(0xffffffffu, i0, 31);
            float S1 = __shfl_sync(0xffffffffu, i1, 31);
            float S2 = __shfl_sync(0xffffffffu, i2, 31);
            float S3 = __shfl_sync(0xffffffffu, i3, 31);

            float G0 = carry;
            float G1 = G0 + S0;
            float G2 = G1 + S1;
            float G3 = G2 + S2;
            carry = G3 + S3;

            float b0 = G0 + (i0 - r0);
            float b1 = G1 + (i1 - r1);
            float b2 = G2 + (i2 - r2);
            float b3 = G3 + (i3 - r3);

            // idx = f*1024 + h*512 + 128j + 4*lane + i
            const float wbase = (float)(T_LEN - (f * CELEMS + h * 512 + 4 * lane));
            float a0 = 0.0f, a1 = 0.0f, a2 = 0.0f, a3 = 0.0f;
            #pragma unroll
            for (int j = 0; j < 4; j++) {
                float bj = (j == 0) ? b0 : (j == 1) ? b1 : (j == 2) ? b2 : b3;
                float wj = wbase - (float)(128 * j);
                a0 = fmaf(fabsf(bj + lp[j][0]), wj,        a0);
                a1 = fmaf(fabsf(bj + lp[j][1]), wj - 1.0f, a1);
                a2 = fmaf(fabsf(bj + lp[j][2]), wj - 2.0f, a2);
                a3 = fmaf(fabsf(bj + lp[j][3]), wj - 3.0f, a3);
            }
            dacc += (double)((a0 + a1) + (a2 + a3));
        }

        // Advance ring: s = f%3, parity flips each wrap.
        if (++s == STAGES) { s = 0; par ^= 1; }
    }

    // Warp reduction of dacc (deterministic).
    #pragma unroll
    for (int o = 16; o > 0; o >>= 1)
        dacc += __shfl_down_sync(0xffffffffu, dacc, o);
    if (lane == 0) {
        g_partial[row] = dacc;
        __threadfence();
        unsigned int prev = atomicAdd(&g_count, 1u);
        is_last = (prev == (unsigned int)(gridDim.x - 1));
    }
    __syncwarp();
    int last = __shfl_sync(0xffffffffu, (int)is_last, 0);

    // Last block: final deterministic reduce of 1024 partials with one warp.
    if (last) {
        if (lane == 0) g_count = 0;   // reset for graph replay
        double v = 0.0;
        #pragma unroll
        for (int j = 0; j < NROWS / 32; j++)
            v += g_partial[lane * (NROWS / 32) + j];
        #pragma unroll
        for (int o = 16; o > 0; o >>= 1)
            v += __shfl_down_sync(0xffffffffu, v, o);
        if (lane == 0) {
            double tc = (double)T_LEN * 16.0;            // T*C
            double scale = 2.0 / (tc * (tc + 1.0));
            out[0] = (float)((v / 64.0) * scale);        // mean over B=64
        }
    }
}

extern "C" void kernel_launch(void* const* d_in, const int* in_sizes, int n_in,
                              void* d_out, int out_size) {
    (void)in_sizes; (void)n_in; (void)out_size;
    const float* y_pred = (const float*)d_in[0];
    const float* y_true = (const float*)d_in[1];
    float* out = (float*)d_out;
    wass_kernel<<<NROWS, 32>>>(y_pred, y_true, out);
}